// round 13
// baseline (speedup 1.0000x reference)
#include <cuda_runtime.h>
#include <cuda_bf16.h>

#define NQ    18
#define NBAT  16

// Sum/difference-basis MPS, forward sweep only (derivation verified R2..R11).
// Pre-distributed site map (constant products folded on the producer side):
//   sd' = z3*dd ; dd' = wx*p + w*sd ; p' = e*p + ey*sd
//   z_i = sd_i + (2*s0_{i+1})*p_i   (post-site-i state; 2.0 terminator at i=17)
// with z3=c1*c0, w=c1, wx=c1*2s0, ey=-s1*0.5s0, e=-s1 (FULL angles).
// Readout is emitted one iteration late: at iter t, incoming state is
// post-site-(t-1) and this site's 2s0 is exactly q01 for site t-1.

__shared__ float4 g_cA[NQ][NBAT];   // {z3, w, wx, ey}
__shared__ float2 g_cB[NQ][NBAT];   // {e, 2*s0}  (all writes thread-local)

__global__ void __launch_bounds__(NQ * NBAT, 1)
quantum_mps_kernel(const float* __restrict__ in, float* __restrict__ out) {
    const int s = threadIdx.x;      // site  0..17
    const int b = threadIdx.y;      // batch 0..15

    // ---- phase 1: one (batch, site) per thread — no integer division
    {
        float s0, c0, s1, c1;
        __sincosf(in[b * 36 + s],      &s0, &c0);   // layer 0
        __sincosf(in[b * 36 + 18 + s], &s1, &c1);   // layer 1
        g_cA[s][b] = make_float4(c1 * c0, c1, c1 * (s0 + s0), -s1 * 0.5f * s0);
        g_cB[s][b] = make_float2(-s1, s0 + s0);
    }
    __syncthreads();

    // ---- phase 2: forward sweep + shifted in-loop readout, warp 0
    const int lin = b * NQ + s;
    if (lin < NBAT) {
        const int bb = lin;
        float sd = 1.0f, dd = 1.0f, p = 0.0f;
        #pragma unroll
        for (int t = 0; t < NQ; t++) {
            const float4 a  = g_cA[t][bb];   // {z3, w, wx, ey}
            const float2 cb = g_cB[t][bb];   // {e, 2*s0}
            if (t > 0)                        // z_{t-1}: off the update chain
                out[bb * NQ + (t - 1)] = fmaf(cb.y, p, sd);
            const float nsd = a.x * dd;
            const float ndd = fmaf(a.z, p, a.y * sd);
            const float np  = fmaf(cb.x, p, a.w * sd);
            sd = nsd; dd = ndd; p = np;
        }
        out[bb * NQ + (NQ - 1)] = fmaf(2.0f, p, sd);
    }
}

extern "C" void kernel_launch(void* const* d_in, const int* in_sizes, int n_in,
                              void* d_out, int out_size) {
    const float* in  = (const float*)d_in[0];
    float*       out = (float*)d_out;
    dim3 blk(NQ, NBAT, 1);
    quantum_mps_kernel<<<1, blk>>>(in, out);
}

// round 14
// speedup vs baseline: 1.4828x; 1.4828x over previous
#include <cuda_runtime.h>
#include <cuda_bf16.h>

#define NQ    18
#define NBAT  16
#define NTHR  (NQ * NBAT)   // 288: one thread per (batch, site)

// Sum/difference-basis MPS, forward sweep only (derivation verified R2..R12).
// Pre-distributed site map (constant products folded on the producer side):
//   sd' = z3*dd ; dd' = wx*p + w*sd ; p' = e*p + ey*sd
//   z_i = sd_i + (2*s0_{i+1})*p_i    (2.0 terminator at i = 17)
// with z3=c1*c0, w=c1, wx=c1*2s0, ey=-s1*0.5s0, e=-s1  (FULL angles).
// Shell is byte-for-byte the R10 structure (fastest harness timing): 1-D
// 288-thread block, sweep on warp 0, unconditional store per iteration.

__shared__ float4 g_cA[NQ][NBAT];   // {z3, w, wx, ey}
__shared__ float2 g_cB[NQ][NBAT];   // {e, 2*s0}   (all writes thread-local)

__global__ void __launch_bounds__(NTHR, 1)
quantum_mps_kernel(const float* __restrict__ in, float* __restrict__ out) {
    const int tid = threadIdx.x;

    // ---- phase 1: one (batch, site) per thread: 2 loads, 2 sincosf, pack
    {
        const int b = tid / NQ, s = tid % NQ;
        float s0, c0, s1, c1;
        __sincosf(in[b * 36 + s],      &s0, &c0);   // layer 0
        __sincosf(in[b * 36 + 18 + s], &s1, &c1);   // layer 1
        g_cA[s][b] = make_float4(c1 * c0, c1, c1 * (s0 + s0), -s1 * 0.5f * s0);
        g_cB[s][b] = make_float2(-s1, s0 + s0);
    }
    __syncthreads();

    // ---- phase 2: forward sweep + in-loop readout, warp 0 (16 lanes)
    if (tid < NBAT) {
        const int b = tid;
        float sd = 1.0f, dd = 1.0f, p = 0.0f;
        #pragma unroll
        for (int t = 0; t < NQ; t++) {
            const float4 a  = g_cA[t][b];   // {z3, w, wx, ey}
            const float  e  = g_cB[t][b].x;
            const float nsd = a.x * dd;
            const float ndd = fmaf(a.z, p, a.y * sd);
            const float np  = fmaf(e,   p, a.w * sd);
            sd = nsd; dd = ndd; p = np;
            // q01 = 2*s0 of site t+1 (thread-local READ of neighbor slot);
            // loop fully unrolled -> ternary resolved at compile time.
            const float q01 = (t < NQ - 1) ? g_cB[t + 1][b].y : 2.0f;
            out[b * NQ + t] = fmaf(q01, p, sd);
        }
    }
}

extern "C" void kernel_launch(void* const* d_in, const int* in_sizes, int n_in,
                              void* d_out, int out_size) {
    const float* in  = (const float*)d_in[0];
    float*       out = (float*)d_out;
    quantum_mps_kernel<<<1, NTHR>>>(in, out);
}